// round 1
// baseline (speedup 1.0000x reference)
#include <cuda_runtime.h>
#include <math.h>

#define B 64
#define NPER 1024
#define NN (B*NPER)        // 65536 nodes
#define EPER (NPER*16)     // 16384 edges per graph
#define EE (B*EPER)        // 1048576 edges
#define H 128

// ---------------- scratch (device globals; no runtime allocation) ----------------
__device__ float g_h[NN*H];
__device__ float g_h2[NN*H];
__device__ float g_agg[NN*H];
__device__ float g_agg4[NN*4];
__device__ float g_score[NN];
__device__ float g_nmask[NN];
__device__ int   g_deg[NN];
__device__ int   g_off[NN];
__device__ int   g_cur[NN];
__device__ int   g_srcs[EE];
__device__ float g_x123[B*2*H];
__device__ float g_invnorm;

// ---------------- init: zero deg, nmask=1, x123=0 ----------------
__global__ void k_init() {
    int t = blockIdx.x * blockDim.x + threadIdx.x;
    if (t < NN) { g_deg[t] = 0; g_nmask[t] = 1.0f; }
    if (t < B*2*H) g_x123[t] = 0.0f;
}

// ---------------- CSR build ----------------
__global__ void k_hist(const int* __restrict__ dst) {
    int e = blockIdx.x * blockDim.x + threadIdx.x;
    if (e < EE) atomicAdd(&g_deg[dst[e]], 1);
}

__global__ void __launch_bounds__(NPER) k_scan() {
    __shared__ int s[NPER];
    int g = blockIdx.x, t = threadIdx.x;
    int node = g * NPER + t;
    int d = g_deg[node];
    s[t] = d;
    __syncthreads();
    for (int off = 1; off < NPER; off <<= 1) {
        int v = (t >= off) ? s[t - off] : 0;
        __syncthreads();
        s[t] += v;
        __syncthreads();
    }
    int o = g * EPER + s[t] - d;   // exclusive scan + per-graph base
    g_off[node] = o;
    g_cur[node] = o;
}

__global__ void k_scatter(const int* __restrict__ src, const int* __restrict__ dst) {
    int e = blockIdx.x * blockDim.x + threadIdx.x;
    if (e < EE) {
        int p = atomicAdd(&g_cur[dst[e]], 1);
        g_srcs[p] = src[e];
    }
}

// ---------------- conv1: 4-wide aggregate + tiny GEMM ----------------
__global__ void k_agg4(const float* __restrict__ x) {
    int n = blockIdx.x * blockDim.x + threadIdx.x;
    if (n >= NN) return;
    int b0 = g_off[n], e0 = b0 + g_deg[n];
    float4 acc = make_float4(0.f, 0.f, 0.f, 0.f);
    for (int e = b0; e < e0; e++) {
        int s = g_srcs[e];
        float4 v = *(const float4*)&x[s * 4];
        acc.x += v.x; acc.y += v.y; acc.z += v.z; acc.w += v.w;
    }
    *(float4*)&g_agg4[n * 4] = acc;
}

__global__ void k_conv1(const float* __restrict__ x, const float* __restrict__ w1r,
                        const float* __restrict__ b1, const float* __restrict__ w1l) {
    __shared__ float wr[4][H], wl[4][H], bb[H];
    int t = threadIdx.x; // 256
    if (t < H) bb[t] = b1[t];
    for (int i = t; i < 4 * H; i += 256) { wr[i >> 7][i & 127] = w1r[i]; wl[i >> 7][i & 127] = w1l[i]; }
    __syncthreads();
    int n = blockIdx.x * 2 + (t >> 7);
    int o = t & 127;
    float4 a  = *(const float4*)&g_agg4[n * 4];
    float4 xv = *(const float4*)&x[n * 4];
    float v = bb[o]
            + a.x  * wr[0][o] + a.y  * wr[1][o] + a.z  * wr[2][o] + a.w  * wr[3][o]
            + xv.x * wl[0][o] + xv.y * wl[1][o] + xv.z * wl[2][o] + xv.w * wl[3][o];
    g_h[n * H + o] = fmaxf(v, 0.0f);   // nmask all 1 at stage 1
}

// ---------------- pooling ----------------
__global__ void k_norm(const float* __restrict__ pw) {
    __shared__ float red[128];
    int t = threadIdx.x;
    float v = pw[t];
    red[t] = v * v;
    __syncthreads();
    for (int s = 64; s > 0; s >>= 1) { if (t < s) red[t] += red[t + s]; __syncthreads(); }
    if (t == 0) g_invnorm = 1.0f / sqrtf(red[0]);
}

__global__ void k_score(const float* __restrict__ h, const float* __restrict__ pw) {
    int gt = blockIdx.x * blockDim.x + threadIdx.x;
    int n = gt >> 5, lane = gt & 31;
    if (n >= NN) return;
    float4 hv = *(const float4*)&h[n * H + lane * 4];
    float4 wv = *(const float4*)&pw[lane * 4];
    float v = hv.x * wv.x + hv.y * wv.y + hv.z * wv.z + hv.w * wv.w;
    #pragma unroll
    for (int o = 16; o > 0; o >>= 1) v += __shfl_down_sync(0xffffffffu, v, o);
    if (lane == 0) g_score[n] = (g_nmask[n] > 0.0f) ? v : -INFINITY;
}

// rank by counting (stable ties by index). Writes nmask (0/1) and scale factor into g_score.
__global__ void __launch_bounds__(NPER) k_rank(int k) {
    __shared__ float s[NPER];
    int g = blockIdx.x, t = threadIdx.x;
    int node = g * NPER + t;
    float my = g_score[node];
    s[t] = my;
    __syncthreads();
    int cnt = 0;
    #pragma unroll 8
    for (int j = 0; j < NPER; j++) {
        float sj = s[j];
        cnt += (sj > my) || (sj == my && j < t);
    }
    bool keep = cnt < k;
    g_nmask[node] = keep ? 1.0f : 0.0f;
    g_score[node] = keep ? tanhf(my * g_invnorm) : 0.0f;
}

// scale h in place by factor, fused with readout (max over kept, mean = sum/k), accumulated into g_x123
__global__ void __launch_bounds__(512) k_scale_readout(float* __restrict__ h, float invk) {
    __shared__ float smx[4][H], ssm[4][H];
    int g = blockIdx.x, t = threadIdx.x;
    int sub = t >> 7, f = t & 127;
    float mx = -INFINITY, sm = 0.0f;
    for (int n0 = sub; n0 < NPER; n0 += 4) {
        int node = g * NPER + n0;
        float fac = g_score[node];
        float msk = g_nmask[node];
        float v = h[node * H + f] * fac;
        h[node * H + f] = v;
        sm += v;                         // dropped nodes contribute exactly 0
        if (msk > 0.0f) mx = fmaxf(mx, v);
    }
    smx[sub][f] = mx; ssm[sub][f] = sm;
    __syncthreads();
    if (sub == 0) {
        mx = fmaxf(fmaxf(smx[0][f], smx[1][f]), fmaxf(smx[2][f], smx[3][f]));
        sm = ssm[0][f] + ssm[1][f] + ssm[2][f] + ssm[3][f];
        g_x123[g * 2 * H + f]     += mx;
        g_x123[g * 2 * H + H + f] += sm * invk;
    }
}

// ---------------- 128-wide aggregation (gather, warp per node) ----------------
__global__ void k_agg128(const float* __restrict__ hin) {
    int gt = blockIdx.x * blockDim.x + threadIdx.x;
    int n = gt >> 5, lane = gt & 31;
    if (n >= NN) return;
    int b0 = g_off[n], e0 = b0 + g_deg[n];
    float4 acc = make_float4(0.f, 0.f, 0.f, 0.f);
    const float4* h4 = (const float4*)hin;
    for (int e = b0; e < e0; e++) {
        int s = g_srcs[e];
        float4 v = h4[s * 32 + lane];
        acc.x += v.x; acc.y += v.y; acc.z += v.z; acc.w += v.w;
    }
    ((float4*)g_agg)[n * 32 + lane] = acc;
}

// ---------------- conv2/3: out = relu([agg|hin] @ [Wr;Wl] + b) * nmask ----------------
// SGEMM M=65536, N=128, K=256. BM=BN=128, BK=16, 256 threads, 8x8 microtile.
__global__ void __launch_bounds__(256) k_conv(
    const float* __restrict__ Aagg, const float* __restrict__ Ah,
    const float* __restrict__ Wr,   const float* __restrict__ Wl,
    const float* __restrict__ bias, float* __restrict__ hout)
{
    __shared__ float As[16][128];
    __shared__ float Bs[16][128];
    __shared__ float bs[128];
    int tid = threadIdx.x;
    int m0 = blockIdx.x * 128;
    if (tid < 128) bs[tid] = bias[tid];
    int tx = tid & 15, ty = tid >> 4;
    int ar = tid >> 2;          // 0..63
    int ak = (tid & 3) << 2;    // 0,4,8,12
    int kb = tid >> 5;          // 0..7
    int nb = (tid & 31) << 2;
    float acc[8][8] = {};
    for (int k0 = 0; k0 < 256; k0 += 16) {
        const float* Asrc = (k0 < 128) ? Aagg : Ah;
        const float* Bsrc = (k0 < 128) ? Wr : Wl;
        int kb0 = k0 & 127;
        float4 a0 = *(const float4*)&Asrc[(m0 + ar) * 128 + kb0 + ak];
        float4 a1 = *(const float4*)&Asrc[(m0 + ar + 64) * 128 + kb0 + ak];
        float4 b0 = *(const float4*)&Bsrc[(kb0 + kb) * 128 + nb];
        float4 b1 = *(const float4*)&Bsrc[(kb0 + kb + 8) * 128 + nb];
        __syncthreads();
        As[ak + 0][ar] = a0.x; As[ak + 1][ar] = a0.y; As[ak + 2][ar] = a0.z; As[ak + 3][ar] = a0.w;
        As[ak + 0][ar + 64] = a1.x; As[ak + 1][ar + 64] = a1.y; As[ak + 2][ar + 64] = a1.z; As[ak + 3][ar + 64] = a1.w;
        *(float4*)&Bs[kb][nb] = b0;
        *(float4*)&Bs[kb + 8][nb] = b1;
        __syncthreads();
        #pragma unroll
        for (int kk = 0; kk < 16; kk++) {
            float4 ra0 = *(const float4*)&As[kk][ty * 8];
            float4 ra1 = *(const float4*)&As[kk][ty * 8 + 4];
            float4 rb0 = *(const float4*)&Bs[kk][tx * 8];
            float4 rb1 = *(const float4*)&Bs[kk][tx * 8 + 4];
            float ra[8] = {ra0.x, ra0.y, ra0.z, ra0.w, ra1.x, ra1.y, ra1.z, ra1.w};
            float rb[8] = {rb0.x, rb0.y, rb0.z, rb0.w, rb1.x, rb1.y, rb1.z, rb1.w};
            #pragma unroll
            for (int i = 0; i < 8; i++)
                #pragma unroll
                for (int j = 0; j < 8; j++)
                    acc[i][j] += ra[i] * rb[j];
        }
    }
    #pragma unroll
    for (int i = 0; i < 8; i++) {
        int m = m0 + ty * 8 + i;
        float nm = g_nmask[m];
        float4 v0, v1;
        v0.x = fmaxf(acc[i][0] + bs[tx * 8 + 0], 0.f) * nm;
        v0.y = fmaxf(acc[i][1] + bs[tx * 8 + 1], 0.f) * nm;
        v0.z = fmaxf(acc[i][2] + bs[tx * 8 + 2], 0.f) * nm;
        v0.w = fmaxf(acc[i][3] + bs[tx * 8 + 3], 0.f) * nm;
        v1.x = fmaxf(acc[i][4] + bs[tx * 8 + 4], 0.f) * nm;
        v1.y = fmaxf(acc[i][5] + bs[tx * 8 + 5], 0.f) * nm;
        v1.z = fmaxf(acc[i][6] + bs[tx * 8 + 6], 0.f) * nm;
        v1.w = fmaxf(acc[i][7] + bs[tx * 8 + 7], 0.f) * nm;
        *(float4*)&hout[m * 128 + tx * 8]     = v0;
        *(float4*)&hout[m * 128 + tx * 8 + 4] = v1;
    }
}

// ---------------- final MLP + log_softmax ----------------
__global__ void k_mlp(const float* __restrict__ w1, const float* __restrict__ bb1,
                      const float* __restrict__ w2, const float* __restrict__ bb2,
                      const float* __restrict__ w3, const float* __restrict__ bb3,
                      float* __restrict__ out) {
    __shared__ float z[256], z1[H], z2[64], z3[7];
    int b = blockIdx.x, t = threadIdx.x; // 128 threads
    z[t]       = g_x123[b * 256 + t];
    z[t + 128] = g_x123[b * 256 + 128 + t];
    __syncthreads();
    float acc = bb1[t];
    for (int k = 0; k < 256; k++) acc += z[k] * w1[k * H + t];
    z1[t] = fmaxf(acc, 0.0f);
    __syncthreads();
    if (t < 64) {
        float a = bb2[t];
        for (int k = 0; k < H; k++) a += z1[k] * w2[k * 64 + t];
        z2[t] = fmaxf(a, 0.0f);
    }
    __syncthreads();
    if (t < 7) {
        float a = bb3[t];
        for (int k = 0; k < 64; k++) a += z2[k] * w3[k * 7 + t];
        z3[t] = a;
    }
    __syncthreads();
    if (t == 0) {
        float m = z3[0];
        for (int c = 1; c < 7; c++) m = fmaxf(m, z3[c]);
        float s = 0.0f;
        for (int c = 0; c < 7; c++) s += expf(z3[c] - m);
        float lse = logf(s);
        for (int c = 0; c < 7; c++) out[b * 7 + c] = z3[c] - m - lse;
    }
}

// ---------------- launch ----------------
extern "C" void kernel_launch(void* const* d_in, const int* in_sizes, int n_in,
                              void* d_out, int out_size) {
    (void)in_sizes; (void)n_in; (void)out_size;
    const float* x   = (const float*)d_in[0];
    const int*   ei  = (const int*)d_in[1];
    const int*   src = ei;
    const int*   dst = ei + EE;
    const float* w1r = (const float*)d_in[2];
    const float* b1  = (const float*)d_in[3];
    const float* w1l = (const float*)d_in[4];
    const float* w2r = (const float*)d_in[5];
    const float* b2  = (const float*)d_in[6];
    const float* w2l = (const float*)d_in[7];
    const float* w3r = (const float*)d_in[8];
    const float* b3  = (const float*)d_in[9];
    const float* w3l = (const float*)d_in[10];
    const float* p1w = (const float*)d_in[11];
    const float* p2w = (const float*)d_in[12];
    const float* wl1 = (const float*)d_in[13];
    const float* bl1 = (const float*)d_in[14];
    const float* wl2 = (const float*)d_in[15];
    const float* bl2 = (const float*)d_in[16];
    const float* wl3 = (const float*)d_in[17];
    const float* bl3 = (const float*)d_in[18];
    float* out = (float*)d_out;

    float *ph, *ph2, *pagg;
    cudaGetSymbolAddress((void**)&ph,   g_h);
    cudaGetSymbolAddress((void**)&ph2,  g_h2);
    cudaGetSymbolAddress((void**)&pagg, g_agg);

    k_init<<<NN / 256, 256>>>();
    k_hist<<<EE / 256, 256>>>(dst);
    k_scan<<<B, NPER>>>();
    k_scatter<<<EE / 256, 256>>>(src, dst);

    // conv1
    k_agg4<<<NN / 256, 256>>>(x);
    k_conv1<<<NN / 2, 256>>>(x, w1r, b1, w1l);

    // pool1 (k=820) + readout1
    k_norm<<<1, 128>>>(p1w);
    k_score<<<NN * 32 / 256, 256>>>(ph, p1w);
    k_rank<<<B, NPER>>>(820);
    k_scale_readout<<<B, 512>>>(ph, 1.0f / 820.0f);

    // conv2
    k_agg128<<<NN * 32 / 256, 256>>>(ph);
    k_conv<<<NN / 128, 256>>>(pagg, ph, w2r, w2l, b2, ph2);

    // pool2 (k=656) + readout2
    k_norm<<<1, 128>>>(p2w);
    k_score<<<NN * 32 / 256, 256>>>(ph2, p2w);
    k_rank<<<B, NPER>>>(656);
    k_scale_readout<<<B, 512>>>(ph2, 1.0f / 656.0f);

    // conv3
    k_agg128<<<NN * 32 / 256, 256>>>(ph2);
    k_conv<<<NN / 128, 256>>>(pagg, ph2, w3r, w3l, b3, ph);

    // pool3 (k=525, reuses p2w) + readout3
    k_norm<<<1, 128>>>(p2w);
    k_score<<<NN * 32 / 256, 256>>>(ph, p2w);
    k_rank<<<B, NPER>>>(525);
    k_scale_readout<<<B, 512>>>(ph, 1.0f / 525.0f);

    // head
    k_mlp<<<B, 128>>>(wl1, bl1, wl2, bl2, wl3, bl3, out);
}

// round 2
// speedup vs baseline: 1.1036x; 1.1036x over previous
#include <cuda_runtime.h>
#include <math.h>
#include <stdint.h>

#define B 64
#define NPER 1024
#define NN (B*NPER)        // 65536 nodes
#define EPER (NPER*16)     // 16384 edges per graph
#define EE (B*EPER)        // 1048576 edges
#define H 128

// ---------------- scratch (device globals; no runtime allocation) ----------------
__device__ float g_h[NN*H];
__device__ float g_h2[NN*H];
__device__ float g_agg[NN*H];
__device__ float g_agg4[NN*4];
__device__ float g_score[NN];
__device__ float g_nmask[NN];
__device__ int   g_deg[NN];
__device__ int   g_off[NN];
__device__ int   g_srcs[EE];
__device__ float g_x123[B*2*H];
__device__ float g_invnorm;

// ---------------- fused CSR build: one block per graph, smem hist+scan+scatter ----------------
__global__ void __launch_bounds__(1024) k_build(const int* __restrict__ src,
                                                const int* __restrict__ dst) {
    __shared__ int cnt[NPER];
    __shared__ int s[NPER];
    int g = blockIdx.x, t = threadIdx.x;
    int e0 = g * EPER;
    int nbase = g * NPER;
    cnt[t] = 0;
    __syncthreads();
    #pragma unroll
    for (int i = t; i < EPER; i += 1024)
        atomicAdd(&cnt[dst[e0 + i] - nbase], 1);
    __syncthreads();
    int d = cnt[t];
    s[t] = d;
    __syncthreads();
    for (int off = 1; off < NPER; off <<= 1) {
        int v = (t >= off) ? s[t - off] : 0;
        __syncthreads();
        s[t] += v;
        __syncthreads();
    }
    int excl = s[t] - d;
    g_off[nbase + t] = e0 + excl;
    g_deg[nbase + t] = d;
    cnt[t] = excl;            // reuse as scatter cursor
    __syncthreads();
    #pragma unroll
    for (int i = t; i < EPER; i += 1024) {
        int dl = dst[e0 + i] - nbase;
        int p = atomicAdd(&cnt[dl], 1);
        g_srcs[e0 + p] = src[e0 + i];
    }
}

// ---------------- conv1: 4-wide aggregate + tiny GEMM ----------------
__global__ void k_agg4(const float* __restrict__ x) {
    int n = blockIdx.x * blockDim.x + threadIdx.x;
    if (n >= NN) return;
    int b0 = g_off[n], e0 = b0 + g_deg[n];
    float4 acc = make_float4(0.f, 0.f, 0.f, 0.f);
    for (int e = b0; e < e0; e++) {
        int sidx = g_srcs[e];
        float4 v = *(const float4*)&x[sidx * 4];
        acc.x += v.x; acc.y += v.y; acc.z += v.z; acc.w += v.w;
    }
    *(float4*)&g_agg4[n * 4] = acc;
}

__global__ void k_conv1(const float* __restrict__ x, const float* __restrict__ w1r,
                        const float* __restrict__ b1, const float* __restrict__ w1l) {
    __shared__ float wr[4][H], wl[4][H], bb[H];
    int t = threadIdx.x; // 256
    if (t < H) bb[t] = b1[t];
    for (int i = t; i < 4 * H; i += 256) { wr[i >> 7][i & 127] = w1r[i]; wl[i >> 7][i & 127] = w1l[i]; }
    __syncthreads();
    int n = blockIdx.x * 2 + (t >> 7);
    int o = t & 127;
    float4 a  = *(const float4*)&g_agg4[n * 4];
    float4 xv = *(const float4*)&x[n * 4];
    float v = bb[o]
            + a.x  * wr[0][o] + a.y  * wr[1][o] + a.z  * wr[2][o] + a.w  * wr[3][o]
            + xv.x * wl[0][o] + xv.y * wl[1][o] + xv.z * wl[2][o] + xv.w * wl[3][o];
    g_h[n * H + o] = fmaxf(v, 0.0f);   // all nodes alive at stage 1
}

// ---------------- pooling ----------------
__global__ void k_norm(const float* __restrict__ pw) {
    __shared__ float red[128];
    int t = threadIdx.x;
    float v = pw[t];
    red[t] = v * v;
    __syncthreads();
    for (int s = 64; s > 0; s >>= 1) { if (t < s) red[t] += red[t + s]; __syncthreads(); }
    if (t == 0) g_invnorm = 1.0f / sqrtf(red[0]);
}

__global__ void k_score(const float* __restrict__ h, const float* __restrict__ pw, int use_mask) {
    int gt = blockIdx.x * blockDim.x + threadIdx.x;
    int n = gt >> 5, lane = gt & 31;
    if (n >= NN) return;
    float4 hv = *(const float4*)&h[n * H + lane * 4];
    float4 wv = *(const float4*)&pw[lane * 4];
    float v = hv.x * wv.x + hv.y * wv.y + hv.z * wv.z + hv.w * wv.w;
    #pragma unroll
    for (int o = 16; o > 0; o >>= 1) v += __shfl_down_sync(0xffffffffu, v, o);
    if (lane == 0) g_score[n] = (!use_mask || g_nmask[n] > 0.0f) ? v : -INFINITY;
}

// rank by counting. 4 blocks per graph x 256 threads.
__global__ void __launch_bounds__(256) k_rank(int k) {
    __shared__ float s[NPER];
    int g = blockIdx.x >> 2, q = blockIdx.x & 3, t = threadIdx.x;
    for (int i = t; i < NPER; i += 256) s[i] = g_score[g * NPER + i];
    __syncthreads();
    int i = q * 256 + t;
    int node = g * NPER + i;
    float my = s[i];
    int cnt = 0;
    #pragma unroll 8
    for (int j = 0; j < NPER; j++) {
        float sj = s[j];
        cnt += (sj > my) || (sj == my && j < i);
    }
    bool keep = cnt < k;
    g_nmask[node] = keep ? 1.0f : 0.0f;
    g_score[node] = keep ? tanhf(my * g_invnorm) : 0.0f;
}

// scale h in place, fused readout (max over kept, mean=sum/k), accumulate into g_x123
__global__ void __launch_bounds__(512) k_scale_readout(float* __restrict__ h, float invk, int accum) {
    __shared__ float smx[4][H], ssm[4][H];
    int g = blockIdx.x, t = threadIdx.x;
    int sub = t >> 7, f = t & 127;
    float mx = -INFINITY, sm = 0.0f;
    for (int n0 = sub; n0 < NPER; n0 += 4) {
        int node = g * NPER + n0;
        float fac = g_score[node];
        float msk = g_nmask[node];
        float v = h[node * H + f] * fac;
        h[node * H + f] = v;
        sm += v;
        if (msk > 0.0f) mx = fmaxf(mx, v);
    }
    smx[sub][f] = mx; ssm[sub][f] = sm;
    __syncthreads();
    if (sub == 0) {
        mx = fmaxf(fmaxf(smx[0][f], smx[1][f]), fmaxf(smx[2][f], smx[3][f]));
        sm = ssm[0][f] + ssm[1][f] + ssm[2][f] + ssm[3][f];
        if (accum) {
            g_x123[g * 2 * H + f]     += mx;
            g_x123[g * 2 * H + H + f] += sm * invk;
        } else {
            g_x123[g * 2 * H + f]     = mx;
            g_x123[g * 2 * H + H + f] = sm * invk;
        }
    }
}

// ---------------- 128-wide aggregation (gather, warp per node, skip dropped) ----------------
__global__ void k_agg128(const float* __restrict__ hin) {
    int gt = blockIdx.x * blockDim.x + threadIdx.x;
    int n = gt >> 5, lane = gt & 31;
    if (n >= NN) return;
    if (g_nmask[n] == 0.0f) return;   // conv epilogue zeroes these rows anyway
    int b0 = g_off[n], e0 = b0 + g_deg[n];
    float4 acc = make_float4(0.f, 0.f, 0.f, 0.f);
    const float4* h4 = (const float4*)hin;
    for (int e = b0; e < e0; e++) {
        int sidx = g_srcs[e];
        float4 v = h4[sidx * 32 + lane];
        acc.x += v.x; acc.y += v.y; acc.z += v.z; acc.w += v.w;
    }
    ((float4*)g_agg)[n * 32 + lane] = acc;
}

// ---------------- tensor-core conv (3xTF32): out = relu([agg|hin]@[Wr;Wl]+b)*nmask --------
__device__ __forceinline__ uint32_t f2tf(float a) {
    uint32_t r;
    asm("cvt.rna.tf32.f32 %0, %1;" : "=r"(r) : "f"(a));
    return r;
}
__device__ __forceinline__ void split_tf32(float a, uint32_t& hi, uint32_t& lo) {
    hi = f2tf(a);
    float rem = a - __uint_as_float(hi);
    lo = f2tf(rem);
}
__device__ __forceinline__ void mma_tf32(float* c, const uint32_t* a, const uint32_t* b) {
    asm volatile(
        "mma.sync.aligned.m16n8k8.row.col.f32.tf32.tf32.f32 "
        "{%0,%1,%2,%3},{%4,%5,%6,%7},{%8,%9},{%0,%1,%2,%3};"
        : "+f"(c[0]), "+f"(c[1]), "+f"(c[2]), "+f"(c[3])
        : "r"(a[0]), "r"(a[1]), "r"(a[2]), "r"(a[3]), "r"(b[0]), "r"(b[1]));
}

// M=65536, N=128, K=256 (concat). BM=128, BN=128, BK=32. 8 warps: 4 (M) x 2 (N).
__global__ void __launch_bounds__(256) k_conv_tc(
    const float* __restrict__ Aagg, const float* __restrict__ Ah,
    const float* __restrict__ Wr,   const float* __restrict__ Wl,
    const float* __restrict__ bias, float* __restrict__ hout)
{
    __shared__ float As[32][136];   // [k][m], pad 136 -> conflict-free frag loads
    __shared__ float Bs[32][136];   // [k][n]
    __shared__ float bs[128];
    int tid = threadIdx.x;
    int m0 = blockIdx.x * 128;
    if (tid < 128) bs[tid] = bias[tid];
    int wid = tid >> 5, lane = tid & 31;
    int wm = wid & 3, wn = wid >> 2;      // warp tile: rows wm*32, cols wn*64
    int grp = lane >> 2, tig = lane & 3;

    float acc[2][8][4];
    #pragma unroll
    for (int i = 0; i < 2; i++)
        #pragma unroll
        for (int j = 0; j < 8; j++)
            #pragma unroll
            for (int e = 0; e < 4; e++) acc[i][j][e] = 0.0f;

    for (int k0 = 0; k0 < 256; k0 += 32) {
        const float* Asrc = (k0 < 128) ? Aagg : Ah;
        const float* Bsrc = (k0 < 128) ? Wr : Wl;
        int kc = k0 & 127;
        __syncthreads();
        // A: 128 rows x 32 cols, transpose into As[k][m]
        #pragma unroll
        for (int it = 0; it < 4; it++) {
            int i = tid + it * 256;
            int r = i >> 3, c4 = (i & 7) * 4;
            float4 v = *(const float4*)&Asrc[(m0 + r) * 128 + kc + c4];
            As[c4 + 0][r] = v.x; As[c4 + 1][r] = v.y;
            As[c4 + 2][r] = v.z; As[c4 + 3][r] = v.w;
        }
        // B: 32 rows x 128 cols, natural layout
        #pragma unroll
        for (int it = 0; it < 4; it++) {
            int i = tid + it * 256;
            int r = i >> 5, c4 = (i & 31) * 4;
            *(float4*)&Bs[r][c4] = *(const float4*)&Bsrc[(kc + r) * 128 + c4];
        }
        __syncthreads();

        #pragma unroll
        for (int k8 = 0; k8 < 4; k8++) {
            int kk = k8 * 8;
            uint32_t abig[2][4], asml[2][4];
            #pragma unroll
            for (int mt = 0; mt < 2; mt++) {
                int m = wm * 32 + mt * 16;
                float a0 = As[kk + tig][m + grp];
                float a1 = As[kk + tig][m + grp + 8];
                float a2 = As[kk + tig + 4][m + grp];
                float a3 = As[kk + tig + 4][m + grp + 8];
                split_tf32(a0, abig[mt][0], asml[mt][0]);
                split_tf32(a1, abig[mt][1], asml[mt][1]);
                split_tf32(a2, abig[mt][2], asml[mt][2]);
                split_tf32(a3, abig[mt][3], asml[mt][3]);
            }
            uint32_t bbig[8][2], bsml[8][2];
            #pragma unroll
            for (int nt = 0; nt < 8; nt++) {
                int n = wn * 64 + nt * 8;
                float b0 = Bs[kk + tig][n + grp];
                float b1 = Bs[kk + tig + 4][n + grp];
                split_tf32(b0, bbig[nt][0], bsml[nt][0]);
                split_tf32(b1, bbig[nt][1], bsml[nt][1]);
            }
            #pragma unroll
            for (int mt = 0; mt < 2; mt++)
                #pragma unroll
                for (int nt = 0; nt < 8; nt++) {
                    mma_tf32(acc[mt][nt], abig[mt], bbig[nt]);
                    mma_tf32(acc[mt][nt], abig[mt], bsml[nt]);
                    mma_tf32(acc[mt][nt], asml[mt], bbig[nt]);
                }
        }
    }

    // epilogue: bias + relu + nmask
    #pragma unroll
    for (int mt = 0; mt < 2; mt++) {
        int mrow = m0 + wm * 32 + mt * 16 + grp;
        float nm0 = g_nmask[mrow];
        float nm1 = g_nmask[mrow + 8];
        #pragma unroll
        for (int nt = 0; nt < 8; nt++) {
            int n = wn * 64 + nt * 8 + tig * 2;
            float2 v0, v1;
            v0.x = fmaxf(acc[mt][nt][0] + bs[n],     0.f) * nm0;
            v0.y = fmaxf(acc[mt][nt][1] + bs[n + 1], 0.f) * nm0;
            v1.x = fmaxf(acc[mt][nt][2] + bs[n],     0.f) * nm1;
            v1.y = fmaxf(acc[mt][nt][3] + bs[n + 1], 0.f) * nm1;
            *(float2*)&hout[mrow * 128 + n]       = v0;
            *(float2*)&hout[(mrow + 8) * 128 + n] = v1;
        }
    }
}

// ---------------- final MLP + log_softmax ----------------
__global__ void k_mlp(const float* __restrict__ w1, const float* __restrict__ bb1,
                      const float* __restrict__ w2, const float* __restrict__ bb2,
                      const float* __restrict__ w3, const float* __restrict__ bb3,
                      float* __restrict__ out) {
    __shared__ float z[256], z1[H], z2[64], z3[7];
    int b = blockIdx.x, t = threadIdx.x; // 128 threads
    z[t]       = g_x123[b * 256 + t];
    z[t + 128] = g_x123[b * 256 + 128 + t];
    __syncthreads();
    float acc = bb1[t];
    for (int k = 0; k < 256; k++) acc += z[k] * w1[k * H + t];
    z1[t] = fmaxf(acc, 0.0f);
    __syncthreads();
    if (t < 64) {
        float a = bb2[t];
        for (int k = 0; k < H; k++) a += z1[k] * w2[k * 64 + t];
        z2[t] = fmaxf(a, 0.0f);
    }
    __syncthreads();
    if (t < 7) {
        float a = bb3[t];
        for (int k = 0; k < 64; k++) a += z2[k] * w3[k * 7 + t];
        z3[t] = a;
    }
    __syncthreads();
    if (t == 0) {
        float m = z3[0];
        for (int c = 1; c < 7; c++) m = fmaxf(m, z3[c]);
        float s = 0.0f;
        for (int c = 0; c < 7; c++) s += expf(z3[c] - m);
        float lse = logf(s);
        for (int c = 0; c < 7; c++) out[b * 7 + c] = z3[c] - m - lse;
    }
}

// ---------------- launch ----------------
extern "C" void kernel_launch(void* const* d_in, const int* in_sizes, int n_in,
                              void* d_out, int out_size) {
    (void)in_sizes; (void)n_in; (void)out_size;
    const float* x   = (const float*)d_in[0];
    const int*   ei  = (const int*)d_in[1];
    const int*   src = ei;
    const int*   dst = ei + EE;
    const float* w1r = (const float*)d_in[2];
    const float* b1  = (const float*)d_in[3];
    const float* w1l = (const float*)d_in[4];
    const float* w2r = (const float*)d_in[5];
    const float* b2  = (const float*)d_in[6];
    const float* w2l = (const float*)d_in[7];
    const float* w3r = (const float*)d_in[8];
    const float* b3  = (const float*)d_in[9];
    const float* w3l = (const float*)d_in[10];
    const float* p1w = (const float*)d_in[11];
    const float* p2w = (const float*)d_in[12];
    const float* wl1 = (const float*)d_in[13];
    const float* bl1 = (const float*)d_in[14];
    const float* wl2 = (const float*)d_in[15];
    const float* bl2 = (const float*)d_in[16];
    const float* wl3 = (const float*)d_in[17];
    const float* bl3 = (const float*)d_in[18];
    float* out = (float*)d_out;

    float *ph, *ph2, *pagg;
    cudaGetSymbolAddress((void**)&ph,   g_h);
    cudaGetSymbolAddress((void**)&ph2,  g_h2);
    cudaGetSymbolAddress((void**)&pagg, g_agg);

    k_build<<<B, 1024>>>(src, dst);

    // conv1
    k_agg4<<<NN / 256, 256>>>(x);
    k_conv1<<<NN / 2, 256>>>(x, w1r, b1, w1l);

    // pool1 (k=820) + readout1 (write)
    k_norm<<<1, 128>>>(p1w);
    k_score<<<NN * 32 / 256, 256>>>(ph, p1w, 0);
    k_rank<<<B * 4, 256>>>(820);
    k_scale_readout<<<B, 512>>>(ph, 1.0f / 820.0f, 0);

    // conv2
    k_agg128<<<NN * 32 / 256, 256>>>(ph);
    k_conv_tc<<<NN / 128, 256>>>(pagg, ph, w2r, w2l, b2, ph2);

    // pool2 (k=656) + readout2
    k_norm<<<1, 128>>>(p2w);
    k_score<<<NN * 32 / 256, 256>>>(ph2, p2w, 1);
    k_rank<<<B * 4, 256>>>(656);
    k_scale_readout<<<B, 512>>>(ph2, 1.0f / 656.0f, 1);

    // conv3
    k_agg128<<<NN * 32 / 256, 256>>>(ph2);
    k_conv_tc<<<NN / 128, 256>>>(pagg, ph2, w3r, w3l, b3, ph);

    // pool3 (k=525, reuses p2w) + readout3
    k_norm<<<1, 128>>>(p2w);
    k_score<<<NN * 32 / 256, 256>>>(ph, p2w, 1);
    k_rank<<<B * 4, 256>>>(525);
    k_scale_readout<<<B, 512>>>(ph, 1.0f / 525.0f, 1);

    // head
    k_mlp<<<B, 128>>>(wl1, bl1, wl2, bl2, wl3, bl3, out);
}

// round 3
// speedup vs baseline: 1.2923x; 1.1710x over previous
#include <cuda_runtime.h>
#include <math.h>
#include <stdint.h>

#define B 64
#define NPER 1024
#define NN (B*NPER)        // 65536 nodes
#define EPER (NPER*16)     // 16384 edges per graph
#define EE (B*EPER)        // 1048576 edges
#define H 128

// ---------------- scratch (device globals; no runtime allocation) ----------------
__device__ float g_h[NN*H];
__device__ float g_h2[NN*H];
__device__ float g_score[NN];
__device__ float g_fac[NN];
__device__ float g_nmask[NN];
__device__ float g_agg4[NN*4];
__device__ int   g_deg[NN];
__device__ int   g_off[NN];
__device__ int   g_srcs[EE];
__device__ float g_x123[B*2*H];
__device__ float g_invnorm;
__device__ uint32_t g_B2hi[256*128], g_B2lo[256*128];
__device__ uint32_t g_B3hi[256*128], g_B3lo[256*128];

// ---------------- tf32 helpers ----------------
__device__ __forceinline__ uint32_t f2tf(float a) {
    uint32_t r;
    asm("cvt.rna.tf32.f32 %0, %1;" : "=r"(r) : "f"(a));
    return r;
}
__device__ __forceinline__ void split_tf32(float a, uint32_t& hi, uint32_t& lo) {
    hi = f2tf(a);
    float rem = a - __uint_as_float(hi);
    lo = f2tf(rem);
}
__device__ __forceinline__ void mma_tf32(float* c, const uint32_t* a, const uint32_t* b) {
    asm volatile(
        "mma.sync.aligned.m16n8k8.row.col.f32.tf32.tf32.f32 "
        "{%0,%1,%2,%3},{%4,%5,%6,%7},{%8,%9},{%0,%1,%2,%3};"
        : "+f"(c[0]), "+f"(c[1]), "+f"(c[2]), "+f"(c[3])
        : "r"(a[0]), "r"(a[1]), "r"(a[2]), "r"(a[3]), "r"(b[0]), "r"(b[1]));
}

// ---------------- weight pre-split: [k=256][n=128] (Wr;Wl) -> [n][k] hi/lo tf32 ----------------
__global__ void k_prepB(const float* __restrict__ Wr, const float* __restrict__ Wl,
                        uint32_t* __restrict__ bhi, uint32_t* __restrict__ blo) {
    int i = blockIdx.x * 256 + threadIdx.x;   // 32768
    int n = i >> 8, k = i & 255;
    float v = (k < 128) ? Wr[k * 128 + n] : Wl[(k - 128) * 128 + n];
    uint32_t hi, lo;
    split_tf32(v, hi, lo);
    bhi[i] = hi; blo[i] = lo;
}

// ---------------- fused CSR build ----------------
__global__ void __launch_bounds__(1024) k_build(const int* __restrict__ src,
                                                const int* __restrict__ dst) {
    __shared__ int cnt[NPER];
    __shared__ int s[NPER];
    int g = blockIdx.x, t = threadIdx.x;
    int e0 = g * EPER;
    int nbase = g * NPER;
    cnt[t] = 0;
    __syncthreads();
    #pragma unroll
    for (int i = t; i < EPER; i += 1024)
        atomicAdd(&cnt[dst[e0 + i] - nbase], 1);
    __syncthreads();
    int d = cnt[t];
    s[t] = d;
    __syncthreads();
    for (int off = 1; off < NPER; off <<= 1) {
        int v = (t >= off) ? s[t - off] : 0;
        __syncthreads();
        s[t] += v;
        __syncthreads();
    }
    int excl = s[t] - d;
    g_off[nbase + t] = e0 + excl;
    g_deg[nbase + t] = d;
    cnt[t] = excl;
    __syncthreads();
    #pragma unroll
    for (int i = t; i < EPER; i += 1024) {
        int dl = dst[e0 + i] - nbase;
        int p = atomicAdd(&cnt[dl], 1);
        g_srcs[e0 + p] = src[e0 + i];
    }
}

// ---------------- conv1: 4-wide aggregate + tiny GEMM + fused score ----------------
__global__ void k_agg4(const float* __restrict__ x) {
    int n = blockIdx.x * blockDim.x + threadIdx.x;
    if (n >= NN) return;
    int b0 = g_off[n], e0 = b0 + g_deg[n];
    float4 acc = make_float4(0.f, 0.f, 0.f, 0.f);
    for (int e = b0; e < e0; e++) {
        int sidx = g_srcs[e];
        float4 v = *(const float4*)&x[sidx * 4];
        acc.x += v.x; acc.y += v.y; acc.z += v.z; acc.w += v.w;
    }
    *(float4*)&g_agg4[n * 4] = acc;
}

__global__ void k_conv1(const float* __restrict__ x, const float* __restrict__ w1r,
                        const float* __restrict__ b1, const float* __restrict__ w1l,
                        const float* __restrict__ p1w) {
    __shared__ float wr[4][H], wl[4][H], bb[H], pws[H];
    __shared__ float red[8];
    int t = threadIdx.x; // 256
    if (t < H) { bb[t] = b1[t]; pws[t] = p1w[t]; }
    for (int i = t; i < 4 * H; i += 256) { wr[i >> 7][i & 127] = w1r[i]; wl[i >> 7][i & 127] = w1l[i]; }
    __syncthreads();
    int n = blockIdx.x * 2 + (t >> 7);
    int o = t & 127;
    float4 a  = *(const float4*)&g_agg4[n * 4];
    float4 xv = *(const float4*)&x[n * 4];
    float v = bb[o]
            + a.x  * wr[0][o] + a.y  * wr[1][o] + a.z  * wr[2][o] + a.w  * wr[3][o]
            + xv.x * wl[0][o] + xv.y * wl[1][o] + xv.z * wl[2][o] + xv.w * wl[3][o];
    v = fmaxf(v, 0.0f);
    g_h[n * H + o] = v;
    // fused score: dot(row, p1w)
    float sv = v * pws[o];
    #pragma unroll
    for (int d = 16; d > 0; d >>= 1) sv += __shfl_down_sync(0xffffffffu, sv, d);
    int wid = t >> 5, lane = t & 31;
    if (lane == 0) red[wid] = sv;
    __syncthreads();
    if (t < 2)
        g_score[blockIdx.x * 2 + t] = red[t * 4] + red[t * 4 + 1] + red[t * 4 + 2] + red[t * 4 + 3];
}

// ---------------- pooling ----------------
__global__ void k_norm(const float* __restrict__ pw) {
    __shared__ float red[128];
    int t = threadIdx.x;
    float v = pw[t];
    red[t] = v * v;
    __syncthreads();
    for (int s = 64; s > 0; s >>= 1) { if (t < s) red[t] += red[t + s]; __syncthreads(); }
    if (t == 0) g_invnorm = 1.0f / sqrtf(red[0]);
}

// rank by counting (scores already -inf for dead nodes). Writes g_nmask + g_fac.
__global__ void __launch_bounds__(256) k_rank(int k) {
    __shared__ float s[NPER];
    int g = blockIdx.x >> 2, q = blockIdx.x & 3, t = threadIdx.x;
    for (int i = t; i < NPER; i += 256) s[i] = g_score[g * NPER + i];
    __syncthreads();
    int i = q * 256 + t;
    int node = g * NPER + i;
    float my = s[i];
    int cnt = 0;
    #pragma unroll 8
    for (int j = 0; j < NPER; j++) {
        float sj = s[j];
        cnt += (sj > my) || (sj == my && j < i);
    }
    bool keep = cnt < k;
    g_nmask[node] = keep ? 1.0f : 0.0f;
    g_fac[node]   = keep ? tanhf(my * g_invnorm) : 0.0f;
}

// read-only readout: max over kept of f*h, mean = sum(f*h)/k; accumulate into g_x123
__global__ void __launch_bounds__(512) k_readout(const float* __restrict__ h, float invk, int accum) {
    __shared__ float smx[4][H], ssm[4][H];
    int g = blockIdx.x, t = threadIdx.x;
    int sub = t >> 7, f = t & 127;
    float mx = -INFINITY, sm = 0.0f;
    for (int n0 = sub; n0 < NPER; n0 += 4) {
        int node = g * NPER + n0;
        float fac = g_fac[node];
        float msk = g_nmask[node];
        float v = h[node * H + f] * fac;
        sm += v;
        if (msk > 0.0f) mx = fmaxf(mx, v);
    }
    smx[sub][f] = mx; ssm[sub][f] = sm;
    __syncthreads();
    if (sub == 0) {
        mx = fmaxf(fmaxf(smx[0][f], smx[1][f]), fmaxf(smx[2][f], smx[3][f]));
        sm = ssm[0][f] + ssm[1][f] + ssm[2][f] + ssm[3][f];
        if (accum) {
            g_x123[g * 2 * H + f]     += mx;
            g_x123[g * 2 * H + H + f] += sm * invk;
        } else {
            g_x123[g * 2 * H + f]     = mx;
            g_x123[g * 2 * H + H + f] = sm * invk;
        }
    }
}

// ---------------- fused gather + tensor-core conv + score epilogue ----------------
// out = relu( gather_sum(f[src]*h[src]) @ Wr + (f[m]*h[m]) @ Wl + b ) * nmask
// score[m] = nmask>0 ? dot(out_row, pw) : -inf
struct ConvSmem {
    float    AgT[128][132];   // gathered agg [m][k]
    float    As2[128][36];    // self chunk [m][kc]
    uint32_t Bhs[128][36];    // B hi [n][kc]
    uint32_t Bls[128][36];    // B lo [n][kc]
    float    bs[128];
    float    pws[128];
    float    sc[128];
};

__global__ void __launch_bounds__(512, 1) k_conv_fused(
    const float* __restrict__ hin,
    const uint32_t* __restrict__ Bhi, const uint32_t* __restrict__ Blo,
    const float* __restrict__ bias, const float* __restrict__ pw,
    float* __restrict__ hout)
{
    extern __shared__ char smem_raw[];
    ConvSmem& S = *reinterpret_cast<ConvSmem*>(smem_raw);
    int tid = threadIdx.x;
    int m0 = blockIdx.x * 128;
    int wid = tid >> 5, lane = tid & 31;

    if (tid < 128) { S.bs[tid] = bias[tid]; S.pws[tid] = pw[tid]; S.sc[tid] = 0.0f; }

    // ---- phase 1: gather agg into AgT[m][k] (scaled by f[src]) ----
    const float4* h4 = (const float4*)hin;
    #pragma unroll
    for (int i = 0; i < 8; i++) {
        int nl = wid * 8 + i;
        int n = m0 + nl;
        float4 acc = make_float4(0.f, 0.f, 0.f, 0.f);
        if (g_nmask[n] > 0.0f) {
            int b0 = g_off[n], e1 = b0 + g_deg[n];
            for (int e = b0; e < e1; e++) {
                int s = g_srcs[e];
                float fs = g_fac[s];
                if (fs != 0.0f) {
                    float4 v = h4[s * 32 + lane];
                    acc.x += fs * v.x; acc.y += fs * v.y;
                    acc.z += fs * v.z; acc.w += fs * v.w;
                }
            }
        }
        *(float4*)&S.AgT[nl][lane * 4] = acc;
    }
    __syncthreads();

    // ---- phase 2: GEMM K=256 (4 chunks from AgT, 4 chunks self from global) ----
    int wm = wid & 3, wn = wid >> 2;
    int grp = lane >> 2, tig = lane & 3;
    float acc[2][4][4];
    #pragma unroll
    for (int a = 0; a < 2; a++)
        #pragma unroll
        for (int b = 0; b < 4; b++)
            #pragma unroll
            for (int c = 0; c < 4; c++) acc[a][b][c] = 0.0f;

    for (int ko = 0; ko < 8; ko++) {
        // stage B chunk (pre-split, pre-transposed [n][256])
        #pragma unroll
        for (int it = 0; it < 2; it++) {
            int j = tid + it * 512;
            int n = j >> 3, c4 = (j & 7) * 4;
            *(uint4*)&S.Bhs[n][c4] = *(const uint4*)&Bhi[n * 256 + ko * 32 + c4];
            *(uint4*)&S.Bls[n][c4] = *(const uint4*)&Blo[n * 256 + ko * 32 + c4];
        }
        if (ko >= 4) {
            #pragma unroll
            for (int it = 0; it < 2; it++) {
                int j = tid + it * 512;
                int r = j >> 3, c4 = (j & 7) * 4;
                float4 v = *(const float4*)&hin[(m0 + r) * 128 + (ko - 4) * 32 + c4];
                float fm = g_fac[m0 + r];
                v.x *= fm; v.y *= fm; v.z *= fm; v.w *= fm;
                *(float4*)&S.As2[r][c4] = v;
            }
        }
        __syncthreads();
        bool self = (ko >= 4);
        int kb = ko * 32;
        #pragma unroll
        for (int k8 = 0; k8 < 4; k8++) {
            int kk = k8 * 8;
            uint32_t ahi[2][4], alo[2][4];
            #pragma unroll
            for (int mt = 0; mt < 2; mt++) {
                int mr = wm * 32 + mt * 16;
                float a0, a1, a2, a3;
                if (!self) {
                    a0 = S.AgT[mr + grp][kb + kk + tig];
                    a1 = S.AgT[mr + grp + 8][kb + kk + tig];
                    a2 = S.AgT[mr + grp][kb + kk + tig + 4];
                    a3 = S.AgT[mr + grp + 8][kb + kk + tig + 4];
                } else {
                    a0 = S.As2[mr + grp][kk + tig];
                    a1 = S.As2[mr + grp + 8][kk + tig];
                    a2 = S.As2[mr + grp][kk + tig + 4];
                    a3 = S.As2[mr + grp + 8][kk + tig + 4];
                }
                split_tf32(a0, ahi[mt][0], alo[mt][0]);
                split_tf32(a1, ahi[mt][1], alo[mt][1]);
                split_tf32(a2, ahi[mt][2], alo[mt][2]);
                split_tf32(a3, ahi[mt][3], alo[mt][3]);
            }
            uint32_t bh[4][2], bl[4][2];
            #pragma unroll
            for (int nt = 0; nt < 4; nt++) {
                int nr = wn * 32 + nt * 8;
                bh[nt][0] = S.Bhs[nr + grp][kk + tig];
                bh[nt][1] = S.Bhs[nr + grp][kk + tig + 4];
                bl[nt][0] = S.Bls[nr + grp][kk + tig];
                bl[nt][1] = S.Bls[nr + grp][kk + tig + 4];
            }
            #pragma unroll
            for (int mt = 0; mt < 2; mt++)
                #pragma unroll
                for (int nt = 0; nt < 4; nt++) {
                    mma_tf32(acc[mt][nt], ahi[mt], bh[nt]);
                    mma_tf32(acc[mt][nt], ahi[mt], bl[nt]);
                    mma_tf32(acc[mt][nt], alo[mt], bh[nt]);
                }
        }
        __syncthreads();
    }

    // ---- phase 3: epilogue (bias+relu+nmask, write hout, fused score) ----
    #pragma unroll
    for (int mt = 0; mt < 2; mt++) {
        int mrow = m0 + wm * 32 + mt * 16 + grp;
        float nm0 = g_nmask[mrow];
        float nm1 = g_nmask[mrow + 8];
        float dot0 = 0.0f, dot1 = 0.0f;
        #pragma unroll
        for (int nt = 0; nt < 4; nt++) {
            int n0 = wn * 32 + nt * 8 + tig * 2;
            float2 v0, v1;
            v0.x = fmaxf(acc[mt][nt][0] + S.bs[n0],     0.f) * nm0;
            v0.y = fmaxf(acc[mt][nt][1] + S.bs[n0 + 1], 0.f) * nm0;
            v1.x = fmaxf(acc[mt][nt][2] + S.bs[n0],     0.f) * nm1;
            v1.y = fmaxf(acc[mt][nt][3] + S.bs[n0 + 1], 0.f) * nm1;
            *(float2*)&hout[mrow * 128 + n0]       = v0;
            *(float2*)&hout[(mrow + 8) * 128 + n0] = v1;
            dot0 += v0.x * S.pws[n0] + v0.y * S.pws[n0 + 1];
            dot1 += v1.x * S.pws[n0] + v1.y * S.pws[n0 + 1];
        }
        // reduce over tig (4 lanes of the quad)
        dot0 += __shfl_xor_sync(0xffffffffu, dot0, 1, 4);
        dot0 += __shfl_xor_sync(0xffffffffu, dot0, 2, 4);
        dot1 += __shfl_xor_sync(0xffffffffu, dot1, 1, 4);
        dot1 += __shfl_xor_sync(0xffffffffu, dot1, 2, 4);
        if (tig == 0) {
            atomicAdd(&S.sc[wm * 32 + mt * 16 + grp],     dot0);
            atomicAdd(&S.sc[wm * 32 + mt * 16 + grp + 8], dot1);
        }
    }
    __syncthreads();
    if (tid < 128) {
        int m = m0 + tid;
        g_score[m] = (g_nmask[m] > 0.0f) ? S.sc[tid] : -INFINITY;
    }
}

// ---------------- final MLP + log_softmax ----------------
__global__ void k_mlp(const float* __restrict__ w1, const float* __restrict__ bb1,
                      const float* __restrict__ w2, const float* __restrict__ bb2,
                      const float* __restrict__ w3, const float* __restrict__ bb3,
                      float* __restrict__ out) {
    __shared__ float z[256], z1[H], z2[64], z3[7];
    int b = blockIdx.x, t = threadIdx.x; // 128 threads
    z[t]       = g_x123[b * 256 + t];
    z[t + 128] = g_x123[b * 256 + 128 + t];
    __syncthreads();
    float acc = bb1[t];
    for (int k = 0; k < 256; k++) acc += z[k] * w1[k * H + t];
    z1[t] = fmaxf(acc, 0.0f);
    __syncthreads();
    if (t < 64) {
        float a = bb2[t];
        for (int k = 0; k < H; k++) a += z1[k] * w2[k * 64 + t];
        z2[t] = fmaxf(a, 0.0f);
    }
    __syncthreads();
    if (t < 7) {
        float a = bb3[t];
        for (int k = 0; k < 64; k++) a += z2[k] * w3[k * 7 + t];
        z3[t] = a;
    }
    __syncthreads();
    if (t == 0) {
        float m = z3[0];
        for (int c = 1; c < 7; c++) m = fmaxf(m, z3[c]);
        float s = 0.0f;
        for (int c = 0; c < 7; c++) s += expf(z3[c] - m);
        float lse = logf(s);
        for (int c = 0; c < 7; c++) out[b * 7 + c] = z3[c] - m - lse;
    }
}

// ---------------- launch ----------------
extern "C" void kernel_launch(void* const* d_in, const int* in_sizes, int n_in,
                              void* d_out, int out_size) {
    (void)in_sizes; (void)n_in; (void)out_size;
    const float* x   = (const float*)d_in[0];
    const int*   ei  = (const int*)d_in[1];
    const int*   src = ei;
    const int*   dst = ei + EE;
    const float* w1r = (const float*)d_in[2];
    const float* b1  = (const float*)d_in[3];
    const float* w1l = (const float*)d_in[4];
    const float* w2r = (const float*)d_in[5];
    const float* b2  = (const float*)d_in[6];
    const float* w2l = (const float*)d_in[7];
    const float* w3r = (const float*)d_in[8];
    const float* b3  = (const float*)d_in[9];
    const float* w3l = (const float*)d_in[10];
    const float* p1w = (const float*)d_in[11];
    const float* p2w = (const float*)d_in[12];
    const float* wl1 = (const float*)d_in[13];
    const float* bl1 = (const float*)d_in[14];
    const float* wl2 = (const float*)d_in[15];
    const float* bl2 = (const float*)d_in[16];
    const float* wl3 = (const float*)d_in[17];
    const float* bl3 = (const float*)d_in[18];
    float* out = (float*)d_out;

    float *ph, *ph2;
    uint32_t *b2hi, *b2lo, *b3hi, *b3lo;
    cudaGetSymbolAddress((void**)&ph,   g_h);
    cudaGetSymbolAddress((void**)&ph2,  g_h2);
    cudaGetSymbolAddress((void**)&b2hi, g_B2hi);
    cudaGetSymbolAddress((void**)&b2lo, g_B2lo);
    cudaGetSymbolAddress((void**)&b3hi, g_B3hi);
    cudaGetSymbolAddress((void**)&b3lo, g_B3lo);

    static int smem_set = 0;
    if (!smem_set) {
        cudaFuncSetAttribute(k_conv_fused, cudaFuncAttributeMaxDynamicSharedMemorySize,
                             (int)sizeof(ConvSmem));
        smem_set = 1;
    }

    k_prepB<<<128, 256>>>(w2r, w2l, b2hi, b2lo);
    k_prepB<<<128, 256>>>(w3r, w3l, b3hi, b3lo);
    k_build<<<B, 1024>>>(src, dst);

    // conv1 + score1
    k_agg4<<<NN / 256, 256>>>(x);
    k_conv1<<<NN / 2, 256>>>(x, w1r, b1, w1l, p1w);

    // pool1 (k=820) + readout1
    k_norm<<<1, 128>>>(p1w);
    k_rank<<<B * 4, 256>>>(820);
    k_readout<<<B, 512>>>(ph, 1.0f / 820.0f, 0);

    // conv2 (fused gather + gemm + score2)
    k_conv_fused<<<NN / 128, 512, sizeof(ConvSmem)>>>(ph, b2hi, b2lo, b2, p2w, ph2);

    // pool2 (k=656) + readout2
    k_norm<<<1, 128>>>(p2w);
    k_rank<<<B * 4, 256>>>(656);
    k_readout<<<B, 512>>>(ph2, 1.0f / 656.0f, 1);

    // conv3 (fused, scores with p2w again)
    k_conv_fused<<<NN / 128, 512, sizeof(ConvSmem)>>>(ph2, b3hi, b3lo, b3, p2w, ph);

    // pool3 (k=525) + readout3
    k_norm<<<1, 128>>>(p2w);
    k_rank<<<B * 4, 256>>>(525);
    k_readout<<<B, 512>>>(ph, 1.0f / 525.0f, 1);

    // head
    k_mlp<<<B, 128>>>(wl1, bl1, wl2, bl2, wl3, bl3, out);
}